// round 4
// baseline (speedup 1.0000x reference)
#include <cuda_runtime.h>
#include <cstdint>

// Problem constants (fixed by the dataset: x is (total, 256, 96, 288))
#define CCH 256            // channels
#define PP  27648          // H*W = 96*288
#define TP  32             // pixels per block tile
#define NT  512            // threads per block
#define NW  16             // warps per block
#define KPT (CCH / NW)     // channels per thread = 16
#define SCALE 0.0625f      // 1/sqrt(256)

__global__ void __launch_bounds__(NT, 2)
att_fusion_kernel(const float* __restrict__ x,
                  const int* __restrict__ record_len,
                  float* __restrict__ out,
                  int B) {
    // Only smem use: per-record partial-score reduction scratch (2 KB).
    __shared__ float sred[NT];

    const int tid  = threadIdx.x;
    const int lane = tid & 31;
    const int wid  = tid >> 5;
    const int c0   = wid * KPT;

    const int b  = blockIdx.y;
    const int p0 = blockIdx.x * TP;

    // Per-batch record count + offset (B is tiny; redundant per-thread is fine)
    int rec = 0, off = 0;
    for (int j = 0; j < B; ++j) {
        int r = __ldg(&record_len[j]);
        if (j < b) off += r;
        if (j == b) rec = r;
    }

    // Thread's fixed element set: channels c0..c0+KPT-1 at pixel p0+lane.
    // Per (warp, k): 32 lanes read 32 consecutive floats -> fully coalesced 128B.
    const float* gbase = x + (size_t)off * CCH * PP + (size_t)c0 * PP + p0 + lane;

    float q_r[KPT];    // query record values (record 0)
    float v_r[KPT];    // current record values
    float acc[KPT];
    float m = -1e30f;
    float d = 0.f;

    for (int l = 0; l < rec; ++l) {
        const float* g = gbase + (size_t)l * CCH * PP;

        // Load this thread's slice of record l directly into registers
        // (16 independent LDG.32 -> high MLP), fold the score dot in.
        float partial = 0.f;
        if (l == 0) {
            #pragma unroll
            for (int k = 0; k < KPT; ++k) {
                float v = __ldg(g + (size_t)k * PP);
                q_r[k] = v;
                v_r[k] = v;
                partial += v * v;
            }
        } else {
            #pragma unroll
            for (int k = 0; k < KPT; ++k) {
                float v = __ldg(g + (size_t)k * PP);
                v_r[k] = v;
                partial += q_r[k] * v;
            }
        }

        sred[tid] = partial;
        __syncthreads();

        // Cross-warp reduce: sum the NW partials for this thread's pixel.
        float ssum = 0.f;
        #pragma unroll
        for (int j = 0; j < NW; ++j) ssum += sred[j * TP + lane];
        float s = ssum * SCALE;

        // Online softmax update + accumulate from registers (no smem tile).
        float mn   = fmaxf(m, s);
        float corr = __expf(m - mn);
        float w    = __expf(s - mn);
        d = d * corr + w;
        m = mn;
        if (l == 0) {
            #pragma unroll
            for (int k = 0; k < KPT; ++k) acc[k] = w * v_r[k];
        } else {
            #pragma unroll
            for (int k = 0; k < KPT; ++k) acc[k] = fmaf(w, v_r[k], acc[k] * corr);
        }
        __syncthreads();   // sred reads done before next record's writes
    }

    // Write out: thread (wid, lane) owns channels c0..c0+KPT-1 at pixel p0+lane
    float inv = 1.f / d;
    size_t obase = ((size_t)b * CCH + c0) * PP + p0 + lane;
    #pragma unroll
    for (int k = 0; k < KPT; ++k) {
        out[obase + (size_t)k * PP] = acc[k] * inv;
    }
}

extern "C" void kernel_launch(void* const* d_in, const int* in_sizes, int n_in,
                              void* d_out, int out_size) {
    const float* x          = (const float*)d_in[0];
    const int*   record_len = (const int*)d_in[1];
    float*       out        = (float*)d_out;
    const int B = in_sizes[1];

    dim3 grid(PP / TP, B);
    att_fusion_kernel<<<grid, NT>>>(x, record_len, out, B);
}

// round 5
// speedup vs baseline: 1.2120x; 1.2120x over previous
#include <cuda_runtime.h>
#include <cstdint>

// Problem constants (fixed by the dataset: x is (total, 256, 96, 288))
#define CCH 256            // channels
#define PP  27648          // H*W = 96*288
#define TP  32             // pixels per block tile
#define NT  256            // threads per block
#define NW  8              // warps per block
#define KPT (CCH / NW)     // channels per thread = 32
#define NB  3              // ring buffers (prefetch depth 2)
#define SCALE 0.0625f      // 1/sqrt(256)

// cp.async helpers
__device__ __forceinline__ void cp_async16(uint32_t saddr, const void* gptr) {
    asm volatile("cp.async.cg.shared.global [%0], [%1], 16;\n" :: "r"(saddr), "l"(gptr));
}
__device__ __forceinline__ void cp_commit() {
    asm volatile("cp.async.commit_group;\n" ::: "memory");
}
template <int N>
__device__ __forceinline__ void cp_wait() {
    asm volatile("cp.async.wait_group %0;\n" :: "n"(N) : "memory");
}

// Stage one record slice x[idx, :, p0:p0+TP] -> smem [C][TP] (float4 granularity)
__device__ __forceinline__ void load_tile(float* sdst, const float* grec, int p0, int tid) {
    uint32_t sbase = (uint32_t)__cvta_generic_to_shared(sdst);
    #pragma unroll
    for (int it = 0; it < (CCH * TP / 4) / NT; ++it) {   // 8 float4 per thread
        int f = tid + it * NT;          // 0..2047
        int c = f >> 3;                 // row (channel)
        int quad = f & 7;               // float4 within row
        const float* g = grec + (size_t)c * PP + p0 + quad * 4;
        cp_async16(sbase + (uint32_t)f * 16u, g);
    }
}

extern __shared__ float smem_dyn[];

__global__ void __launch_bounds__(NT, 2)
att_fusion_kernel(const float* __restrict__ x,
                  const int* __restrict__ record_len,
                  float* __restrict__ out,
                  int B) {
    // Dynamic smem layout:
    //   xb[3] : CCH*TP floats each (3-stage ring of record tiles)
    //   sred  : NT floats (score reduction scratch)
    float* sred = smem_dyn + NB * CCH * TP;

    const int tid  = threadIdx.x;
    const int lane = tid & 31;
    const int wid  = tid >> 5;
    const int c0   = wid * KPT;

    const int b  = blockIdx.y;
    const int p0 = blockIdx.x * TP;

    // Per-batch record count + offset (B is tiny; redundant per-thread is fine)
    int rec = 0, off = 0;
    for (int j = 0; j < B; ++j) {
        int r = __ldg(&record_len[j]);
        if (j < b) off += r;
        if (j == b) rec = r;
    }

    const float* xbase = x + (size_t)off * CCH * PP;

    // Prologue: fill the ring up to depth 3 (records 0,1,2)
    load_tile(smem_dyn + 0 * CCH * TP, xbase, p0, tid);
    cp_commit();
    if (rec > 1) {
        load_tile(smem_dyn + 1 * CCH * TP, xbase + (size_t)1 * CCH * PP, p0, tid);
        cp_commit();
    }
    if (rec > 2) {
        load_tile(smem_dyn + 2 * CCH * TP, xbase + (size_t)2 * CCH * PP, p0, tid);
        cp_commit();
    }

    float q_r[KPT];
    float acc[KPT];
    float m = -1e30f;
    float d = 0.f;

    for (int l = 0; l < rec; ++l) {
        // Wait for tile l: leave up to 2 newer prefetch groups in flight.
        int rem = rec - 1 - l;
        if (rem >= 2)      cp_wait<2>();
        else if (rem == 1) cp_wait<1>();
        else               cp_wait<0>();
        __syncthreads();

        const float* xs = smem_dyn + (l % NB) * CCH * TP;

        // Partial score over this thread's 32 channels for pixel `lane`
        float partial = 0.f;
        if (l == 0) {
            #pragma unroll
            for (int k = 0; k < KPT; ++k) {
                float v = xs[(c0 + k) * TP + lane];
                q_r[k] = v;
                partial += v * v;
            }
        } else {
            #pragma unroll
            for (int k = 0; k < KPT; ++k) {
                partial += q_r[k] * xs[(c0 + k) * TP + lane];
            }
        }
        sred[tid] = partial;
        __syncthreads();

        // Cross-warp reduce: each thread sums the 8 partials for its pixel
        float ssum = 0.f;
        #pragma unroll
        for (int j = 0; j < NW; ++j) ssum += sred[j * TP + lane];
        float s = ssum * SCALE;

        // Online softmax update + accumulate
        float mn   = fmaxf(m, s);
        float corr = __expf(m - mn);
        float w    = __expf(s - mn);
        d = d * corr + w;
        m = mn;
        if (l == 0) {
            // Query tile already in registers — no smem read needed.
            #pragma unroll
            for (int k = 0; k < KPT; ++k) acc[k] = w * q_r[k];
        } else {
            #pragma unroll
            for (int k = 0; k < KPT; ++k) {
                acc[k] = fmaf(w, xs[(c0 + k) * TP + lane], acc[k] * corr);
            }
        }
        __syncthreads();   // all reads of xs done before reusing this ring slot

        // Refill the slot just consumed with record l+3.
        if (l + NB < rec) {
            load_tile(smem_dyn + ((l + NB) % NB) * CCH * TP,
                      xbase + (size_t)(l + NB) * CCH * PP, p0, tid);
            cp_commit();
        }
    }

    // Write out: thread (wid, lane) owns channels c0..c0+31 at pixel p0+lane
    float inv = 1.f / d;
    size_t obase = ((size_t)b * CCH + c0) * PP + p0 + lane;
    #pragma unroll
    for (int k = 0; k < KPT; ++k) {
        out[obase + (size_t)k * PP] = acc[k] * inv;
    }
}

extern "C" void kernel_launch(void* const* d_in, const int* in_sizes, int n_in,
                              void* d_out, int out_size) {
    const float* x          = (const float*)d_in[0];
    const int*   record_len = (const int*)d_in[1];
    float*       out        = (float*)d_out;
    const int B = in_sizes[1];

    const size_t smem = (size_t)(NB * CCH * TP + NT) * sizeof(float);  // ~97.25 KB
    cudaFuncSetAttribute(att_fusion_kernel,
                         cudaFuncAttributeMaxDynamicSharedMemorySize, (int)smem);

    dim3 grid(PP / TP, B);
    att_fusion_kernel<<<grid, NT, smem>>>(x, record_len, out, B);
}